// round 1
// baseline (speedup 1.0000x reference)
#include <cuda_runtime.h>
#include <math.h>

#define H 96
#define W 96
#define HW 9216
#define NB 2
#define CIN 256
#define CH 64

// ---------------- scratch (device globals; no allocation allowed) ----------
__device__ float g_xh  [NB*CH*HW];
__device__ float g_om  [NB*27*HW];
__device__ float g_z   [NB*CH*HW];
__device__ float g_r   [NB*CH*HW];
__device__ float g_xt  [NB*CH*HW];
__device__ float g_xenh[NB*CH*HW];

// ---------------------------------------------------------------------------
// conv3x3, SAME, NCHW, input = concat(src0[C0], src1[Cin-C0]) on channel dim.
// Block: 256 threads computes OCT out-channels x 8x8 spatial tile.
// Each thread: 4 oc x P px register tile (P = OCT/16).
// grid: (144 tiles, ceil(Cout/OCT), N)
// ---------------------------------------------------------------------------
template<int OCT>
__global__ void conv3x3_kernel(const float* __restrict__ src0,
                               const float* __restrict__ src1,
                               int C0, int Cin,
                               const float* __restrict__ wgt,   // (Cout,Cin,3,3)
                               const float* __restrict__ bias,  // (Cout)
                               float* __restrict__ out, int Cout)
{
    constexpr int P  = OCT / 16;   // px per thread (4 or 2)
    constexpr int PG = 64 / P;     // px groups
    __shared__ float sIn[400];                       // 4ch x 10x10
    __shared__ __align__(16) float sW[4*9*OCT];

    const int tile = blockIdx.x;
    const int ty0  = (tile / 12) * 8;
    const int tx0  = (tile % 12) * 8;
    const int n    = blockIdx.z;
    const int ocBase = blockIdx.y * OCT;
    const int tid  = threadIdx.x;
    const int ocg  = tid / PG;          // 0..OCT/4-1
    const int pxg  = tid % PG;
    const int p0   = pxg * P;
    const int prow = p0 >> 3;
    const int pcol = p0 & 7;
    const int C1   = Cin - C0;

    float acc[4][P];
#pragma unroll
    for (int i = 0; i < 4; i++)
#pragma unroll
        for (int j = 0; j < P; j++) acc[i][j] = 0.f;

    for (int c0 = 0; c0 < Cin; c0 += 4) {
        // stage input patch: 4 channels x 10x10 (zero-padded SAME)
        for (int idx = tid; idx < 400; idx += 256) {
            int cc  = idx / 100;
            int rem = idx % 100;
            int r = rem / 10, cl = rem % 10;
            int gy = ty0 + r - 1, gx = tx0 + cl - 1;
            float v = 0.f;
            if ((unsigned)gy < H && (unsigned)gx < W) {
                int ch = c0 + cc;
                const float* sp = (ch < C0) ? (src0 + ((size_t)n*C0 + ch)*HW)
                                            : (src1 + ((size_t)n*C1 + (ch - C0))*HW);
                v = sp[gy*W + gx];
            }
            sIn[idx] = v;
        }
        // stage weights: sW[(cc*9+kk)*OCT + oc]
        for (int idx = tid; idx < 4*9*OCT; idx += 256) {
            int cc = idx / (9*OCT);
            int kk = (idx / OCT) % 9;
            int oc = idx % OCT;
            int go = ocBase + oc;
            sW[idx] = (go < Cout) ? wgt[((size_t)go*Cin + (c0+cc))*9 + kk] : 0.f;
        }
        __syncthreads();
#pragma unroll
        for (int cc = 0; cc < 4; cc++) {
#pragma unroll
            for (int ky = 0; ky < 3; ky++) {
                const float* irow = &sIn[cc*100 + (prow+ky)*10 + pcol];
                float inr[P+2];
#pragma unroll
                for (int t = 0; t < P+2; t++) inr[t] = irow[t];
#pragma unroll
                for (int kx = 0; kx < 3; kx++) {
                    const float4 w4 = *reinterpret_cast<const float4*>(
                        &sW[(cc*9 + ky*3 + kx)*OCT + (ocg<<2)]);
#pragma unroll
                    for (int j = 0; j < P; j++) {
                        float iv = inr[kx+j];
                        acc[0][j] = fmaf(w4.x, iv, acc[0][j]);
                        acc[1][j] = fmaf(w4.y, iv, acc[1][j]);
                        acc[2][j] = fmaf(w4.z, iv, acc[2][j]);
                        acc[3][j] = fmaf(w4.w, iv, acc[3][j]);
                    }
                }
            }
        }
        __syncthreads();
    }
#pragma unroll
    for (int i = 0; i < 4; i++) {
        int go = ocBase + (ocg<<2) + i;
        if (go < Cout) {
            float b = bias[go];
#pragma unroll
            for (int j = 0; j < P; j++) {
                out[((size_t)n*Cout + go)*HW + (ty0+prow)*W + tx0 + pcol + j]
                    = acc[i][j] + b;
            }
        }
    }
}

// ---------------------------------------------------------------------------
// DCN main: bilinear-gather samples from concat(src0,src1) [128 ch] using
// offsets om (N,27,HW: dy[9],dx[9],mask[9]); GEMM with w (64,128,9); bias;
// activation (0=sigmoid, 1=tanh).
// Block: 256 threads, 8x8 px tile x 64 oc. Dynamic smem.
// ---------------------------------------------------------------------------
#define DCN_SMEM 55296
extern __shared__ float dynsmem[];

__global__ void dcn_kernel(const float* __restrict__ src0,
                           const float* __restrict__ src1,
                           const float* __restrict__ om,
                           const float* __restrict__ wgt,
                           const float* __restrict__ bias,
                           float* __restrict__ out, int act)
{
    float* sWgt = dynsmem;                    // 2304 f  (4 bilinear wgts x 9k x 64px)
    int*   sOff = (int*)(dynsmem + 2304);     // 2304 i
    float* sS   = dynsmem + 4608;             // 4608 f  (72 x 64)
    float* sWt  = dynsmem + 9216;             // 4608 f  (72 x 64)

    const int tile = blockIdx.x;
    const int n    = blockIdx.z;
    const int ty0  = (tile / 12) * 8;
    const int tx0  = (tile % 12) * 8;
    const int tid  = threadIdx.x;

    // ---- precompute per-(k,px) clamped corner offsets + (bilinear*mask) wgts
    for (int idx = tid; idx < 576; idx += 256) {
        int k = idx >> 6, p = idx & 63;
        int py = ty0 + (p >> 3), px = tx0 + (p & 7);
        int pix = py*W + px;
        float dy = om[((size_t)n*27 + k     )*HW + pix];
        float dx = om[((size_t)n*27 + 9  + k)*HW + pix];
        float mv = om[((size_t)n*27 + 18 + k)*HW + pix];
        float m  = 1.f / (1.f + __expf(-mv));
        float fy = (float)(py + (k/3) - 1) + dy;
        float fx = (float)(px + (k%3) - 1) + dx;
        float y0f = floorf(fy), x0f = floorf(fx);
        float wy = fy - y0f, wx = fx - x0f;
        y0f = fmaxf(fminf(y0f, 1.0e4f), -1.0e4f);
        x0f = fmaxf(fminf(x0f, 1.0e4f), -1.0e4f);
        int iy0 = (int)y0f, ix0 = (int)x0f;
        int iy1 = iy0 + 1,  ix1 = ix0 + 1;
        bool vy0 = (unsigned)iy0 < H, vy1 = (unsigned)iy1 < H;
        bool vx0 = (unsigned)ix0 < W, vx1 = (unsigned)ix1 < W;
        int cy0 = min(max(iy0,0),H-1), cy1 = min(max(iy1,0),H-1);
        int cx0 = min(max(ix0,0),W-1), cx1 = min(max(ix1,0),W-1);
        int b = idx << 2;
        sOff[b+0] = cy0*W + cx0;  sWgt[b+0] = (vy0 && vx0) ? (1.f-wy)*(1.f-wx)*m : 0.f;
        sOff[b+1] = cy0*W + cx1;  sWgt[b+1] = (vy0 && vx1) ? (1.f-wy)*wx*m       : 0.f;
        sOff[b+2] = cy1*W + cx0;  sWgt[b+2] = (vy1 && vx0) ? wy*(1.f-wx)*m       : 0.f;
        sOff[b+3] = cy1*W + cx1;  sWgt[b+3] = (vy1 && vx1) ? wy*wx*m             : 0.f;
    }
    __syncthreads();

    const int ocg = tid >> 4;   // 0..15 (4 oc each)
    const int pxg = tid & 15;   // 0..15 (4 px each)
    float acc[4][4];
#pragma unroll
    for (int i = 0; i < 4; i++)
#pragma unroll
        for (int j = 0; j < 4; j++) acc[i][j] = 0.f;

    for (int ch0 = 0; ch0 < 128; ch0 += 8) {
        // stage gathered samples: sS[(cl*9+k)*64 + p]
        for (int idx = tid; idx < 4608; idx += 256) {
            int cl = idx / 576;
            int kp = idx % 576;
            int c  = ch0 + cl;
            const float* sp = (c < 64) ? (src0 + ((size_t)n*64 + c   )*HW)
                                       : (src1 + ((size_t)n*64 + c-64)*HW);
            int b = kp << 2;
            float v = sWgt[b+0] * __ldg(sp + sOff[b+0])
                    + sWgt[b+1] * __ldg(sp + sOff[b+1])
                    + sWgt[b+2] * __ldg(sp + sOff[b+2])
                    + sWgt[b+3] * __ldg(sp + sOff[b+3]);
            sS[idx] = v;
        }
        // stage weights: sWt[(cl*9+k)*64 + oc] = wgt[(oc*128 + c)*9 + k]
        for (int idx = tid; idx < 4608; idx += 256) {
            int kk = idx >> 6;
            int oc = idx & 63;
            int cl = kk / 9, k = kk % 9;
            sWt[idx] = wgt[((size_t)oc*128 + ch0 + cl)*9 + k];
        }
        __syncthreads();
#pragma unroll 4
        for (int kk = 0; kk < 72; kk++) {
            const float4 w4 = *reinterpret_cast<const float4*>(&sWt[kk*64 + (ocg<<2)]);
            const float4 s4 = *reinterpret_cast<const float4*>(&sS [kk*64 + (pxg<<2)]);
            acc[0][0] = fmaf(w4.x, s4.x, acc[0][0]);
            acc[0][1] = fmaf(w4.x, s4.y, acc[0][1]);
            acc[0][2] = fmaf(w4.x, s4.z, acc[0][2]);
            acc[0][3] = fmaf(w4.x, s4.w, acc[0][3]);
            acc[1][0] = fmaf(w4.y, s4.x, acc[1][0]);
            acc[1][1] = fmaf(w4.y, s4.y, acc[1][1]);
            acc[1][2] = fmaf(w4.y, s4.z, acc[1][2]);
            acc[1][3] = fmaf(w4.y, s4.w, acc[1][3]);
            acc[2][0] = fmaf(w4.z, s4.x, acc[2][0]);
            acc[2][1] = fmaf(w4.z, s4.y, acc[2][1]);
            acc[2][2] = fmaf(w4.z, s4.z, acc[2][2]);
            acc[2][3] = fmaf(w4.z, s4.w, acc[2][3]);
            acc[3][0] = fmaf(w4.w, s4.x, acc[3][0]);
            acc[3][1] = fmaf(w4.w, s4.y, acc[3][1]);
            acc[3][2] = fmaf(w4.w, s4.z, acc[3][2]);
            acc[3][3] = fmaf(w4.w, s4.w, acc[3][3]);
        }
        __syncthreads();
    }

    const int p0 = pxg << 2;
    const int oy = ty0 + (p0 >> 3);
    const int ox = tx0 + (p0 & 7);
#pragma unroll
    for (int i = 0; i < 4; i++) {
        int oc = (ocg<<2) + i;
        float b = bias[oc];
#pragma unroll
        for (int j = 0; j < 4; j++) {
            float v = acc[i][j] + b;
            v = (act == 0) ? (1.f / (1.f + __expf(-v))) : tanhf(v);
            out[((size_t)n*64 + oc)*HW + oy*W + ox + j] = v;
        }
    }
}

// ---------------------------------------------------------------------------
// NCF: 49-tap (r=3, dil=2) correlation softmax-attention sample.
// Block 256 threads = 64 pixels x 4 channel-groups (16 ch each).
// corr reduced across channel-groups via warp shuffles (lanes xor 1, xor 2).
// ---------------------------------------------------------------------------
__global__ void ncf_kernel(const float* __restrict__ f1,
                           const float* __restrict__ f2,
                           float* __restrict__ rout)
{
    const int tid = threadIdx.x;
    const int cg  = tid & 3;
    const int pl  = tid >> 2;
    const int gp  = blockIdx.x * 64 + pl;   // 0 .. N*HW-1
    const int n   = gp / HW;
    const int pix = gp % HW;
    const int y   = pix / W, x = pix % W;

    // validity per tap
    unsigned long long vmask = 0ull;
#pragma unroll
    for (int k = 0; k < 49; k++) {
        int yy = y + (k/7)*2 - 6;
        int xx = x + (k%7)*2 - 6;
        if ((unsigned)yy < H && (unsigned)xx < W) vmask |= (1ull << k);
    }

    float corr[49];
#pragma unroll
    for (int k = 0; k < 49; k++) corr[k] = 0.f;

    const float* f1b = f1 + (size_t)n*64*HW + pix;
    const float* f2b = f2 + (size_t)n*64*HW + pix;

#pragma unroll 1
    for (int ci = 0; ci < 16; ci++) {
        int c = cg*16 + ci;
        float a = f1b[(size_t)c*HW];
        const float* fp = f2b + (size_t)c*HW;
#pragma unroll
        for (int k = 0; k < 49; k++) {
            int off = ((k/7)*2 - 6)*W + (k%7)*2 - 6;
            float v = ((vmask >> k) & 1ull) ? __ldg(fp + off) : 0.f;
            corr[k] = fmaf(a, v, corr[k]);
        }
    }
    // reduce across the 4 channel groups (consecutive lanes)
#pragma unroll
    for (int k = 0; k < 49; k++) {
        corr[k] += __shfl_xor_sync(0xffffffffu, corr[k], 1);
        corr[k] += __shfl_xor_sync(0xffffffffu, corr[k], 2);
        corr[k] *= 0.125f;   // 1/sqrt(64)
    }
    // softmax over 49 taps
    float mx = corr[0];
#pragma unroll
    for (int k = 1; k < 49; k++) mx = fmaxf(mx, corr[k]);
    float s = 0.f;
#pragma unroll
    for (int k = 0; k < 49; k++) { corr[k] = __expf(corr[k] - mx); s += corr[k]; }
    float inv = 1.f / s;
#pragma unroll
    for (int k = 0; k < 49; k++) corr[k] *= inv;

    // attention-weighted sample, 16 channels per thread
#pragma unroll 1
    for (int ci = 0; ci < 16; ci++) {
        int c = cg*16 + ci;
        const float* fp = f2b + (size_t)c*HW;
        float av = 0.f;
#pragma unroll
        for (int k = 0; k < 49; k++) {
            int off = ((k/7)*2 - 6)*W + (k%7)*2 - 6;
            float v = ((vmask >> k) & 1ull) ? __ldg(fp + off) : 0.f;
            av = fmaf(corr[k], v, av);
        }
        rout[((size_t)n*64 + c)*HW + pix] = av;
    }
}

// ---------------------------------------------------------------------------
__global__ void combine_kernel(const float* __restrict__ z,
                               const float* __restrict__ t,
                               const float* __restrict__ xt,
                               float* __restrict__ out, int total)
{
    int i = blockIdx.x * 256 + threadIdx.x;
    if (i < total) {
        float zz = z[i];
        out[i] = (1.f - zz) * t[i] + zz * xt[i];
    }
}

// ---------------------------------------------------------------------------
extern "C" void kernel_launch(void* const* d_in, const int* in_sizes, int n_in,
                              void* d_out, int out_size)
{
    const float* X    = (const float*)d_in[0];
    const float* T    = (const float*)d_in[1];
    const float* Wi   = (const float*)d_in[2];
    const float* Bi   = (const float*)d_in[3];
    const float* Wo   = (const float*)d_in[4];
    const float* Bo   = (const float*)d_in[5];
    const float* EZW  = (const float*)d_in[6];
    const float* EZB  = (const float*)d_in[7];
    const float* EZOW = (const float*)d_in[8];
    const float* EZOB = (const float*)d_in[9];
    const float* EHW  = (const float*)d_in[10];
    const float* EHB  = (const float*)d_in[11];
    const float* EHOW = (const float*)d_in[12];
    const float* EHOB = (const float*)d_in[13];
    const float* UZW  = (const float*)d_in[14];
    const float* UZB  = (const float*)d_in[15];
    const float* UZOW = (const float*)d_in[16];
    const float* UZOB = (const float*)d_in[17];
    const float* UHW  = (const float*)d_in[18];
    const float* UHB  = (const float*)d_in[19];
    const float* UHOW = (const float*)d_in[20];
    const float* UHOB = (const float*)d_in[21];

    float* out  = (float*)d_out;
    float* newt = out + (size_t)NB*CIN*HW;

    float *xh, *om, *zb, *rb, *xt, *xe;
    cudaGetSymbolAddress((void**)&xh, g_xh);
    cudaGetSymbolAddress((void**)&om, g_om);
    cudaGetSymbolAddress((void**)&zb, g_z);
    cudaGetSymbolAddress((void**)&rb, g_r);
    cudaGetSymbolAddress((void**)&xt, g_xt);
    cudaGetSymbolAddress((void**)&xe, g_xenh);

    cudaFuncSetAttribute(dcn_kernel,
                         cudaFuncAttributeMaxDynamicSharedMemorySize, DCN_SMEM);

    dim3 g144(144, 1, NB);

    // xh = conv_in(x)
    conv3x3_kernel<64><<<g144, 256>>>(X, X, CIN, CIN, Wi, Bi, xh, CH);

    // ---- enh branch: stargru(x=template, t=xh) ----
    conv3x3_kernel<32><<<g144, 256>>>(T, xh, CH, 2*CH, EZOW, EZOB, om, 27);
    dcn_kernel<<<g144, 256, DCN_SMEM>>>(T, xh, om, EZW, EZB, zb, 0);
    ncf_kernel<<<NB*HW/64, 256>>>(xh, T, rb);
    conv3x3_kernel<32><<<g144, 256>>>(rb, xh, CH, 2*CH, EHOW, EHOB, om, 27);
    dcn_kernel<<<g144, 256, DCN_SMEM>>>(rb, xh, om, EHW, EHB, xt, 1);
    combine_kernel<<<(NB*CH*HW)/256, 256>>>(zb, xh, xt, xe, NB*CH*HW);

    // out = conv_out(x_enh)   (independent of upd branch)
    conv3x3_kernel<64><<<dim3(144, 4, NB), 256>>>(xe, xe, CH, CH, Wo, Bo, out, CIN);

    // ---- upd branch: stargru(x=xh, t=template) ----
    conv3x3_kernel<32><<<g144, 256>>>(xh, T, CH, 2*CH, UZOW, UZOB, om, 27);
    dcn_kernel<<<g144, 256, DCN_SMEM>>>(xh, T, om, UZW, UZB, zb, 0);
    ncf_kernel<<<NB*HW/64, 256>>>(T, xh, rb);
    conv3x3_kernel<32><<<g144, 256>>>(rb, T, CH, 2*CH, UHOW, UHOB, om, 27);
    dcn_kernel<<<g144, 256, DCN_SMEM>>>(rb, T, om, UHW, UHB, xt, 1);
    combine_kernel<<<(NB*CH*HW)/256, 256>>>(zb, T, xt, newt, NB*CH*HW);
}